// round 4
// baseline (speedup 1.0000x reference)
#include <cuda_runtime.h>

// Problem: x (2,128,512,512) f32.
//   edge = sum_o |conv(sum_c x, sobel_o)|  (channel-independent)
//   out  = maxpool2x2(edge) broadcast to (2,128,256,256)
//
// K1: channel sum (reads 256MB)  -> g_sum (2,512,512)
// K2: per (b, pooled row): stage 4 g_sum rows in smem (coalesced float4),
//     sobel x4 + abs-sum + maxpool from smem, broadcast-write 128 channels
//     with streaming stores (64MB, L2-write bound).

#define S_SPATIAL   (512 * 512)       // 262144
#define S_SPATIAL4  (S_SPATIAL / 4)   // 65536
#define NCH         128
#define NB          2

__device__ float g_sum[NB * S_SPATIAL];     // 2 MB scratch

// ---------------- K1: channel sum (float4) ----------------
__global__ void __launch_bounds__(256) k_chansum(const float4* __restrict__ x) {
    int idx = blockIdx.x * blockDim.x + threadIdx.x;   // 0 .. 131071
    if (idx >= NB * S_SPATIAL4) return;
    int b  = idx >> 16;
    int sp = idx & 0xFFFF;
    const float4* p = x + (size_t)b * NCH * S_SPATIAL4 + sp;
    float4 acc = make_float4(0.f, 0.f, 0.f, 0.f);
#pragma unroll 8
    for (int c = 0; c < NCH; c++) {
        float4 v = p[(size_t)c * S_SPATIAL4];
        acc.x += v.x; acc.y += v.y; acc.z += v.z; acc.w += v.w;
    }
    ((float4*)g_sum)[idx] = acc;
}

// ---------------- K2 fused: smem-staged edge+pool row -> broadcast ----------------
__device__ __forceinline__ float edge_at(const float* r0, const float* r1,
                                         const float* r2, int x0) {
    float a = r0[x0],   bb = r0[x0+1], c = r0[x0+2];
    float d = r1[x0],                   f = r1[x0+2];
    float g = r2[x0],   h = r2[x0+1],  i = r2[x0+2];
    // XLA conv = cross-correlation (no kernel flip)
    float e0 = -a + c - 2.f*d + 2.f*f - g + i;
    float e1 =  a + 2.f*bb + c - g - 2.f*h - i;
    float e2 =  2.f*a + bb + d - f - h - 2.f*i;
    float e3 = -bb - 2.f*c + d - f + 2.f*g + h;
    return fabsf(e0) + fabsf(e1) + fabsf(e2) + fabsf(e3);
}

#define SROW_W 520   // 514 used (x = -1 .. 512), padded

__global__ void __launch_bounds__(256) k_edgecast(float4* __restrict__ out) {
    // grid = NB * 256. block = (b, pooled row py)
    int py = blockIdx.x & 255;
    int b  = blockIdx.x >> 8;
    int tid = threadIdx.x;           // = px, 0..255

    __shared__ float srow[4][SROW_W];   // input rows 2*py-1 .. 2*py+2, x index +1
    __shared__ float row[256];          // pooled edge row

    // Stage 4 rows of g_sum, coalesced float4 (512 float4 total, 2/thread)
    const float* s = g_sum + b * S_SPATIAL;
#pragma unroll
    for (int k = tid; k < 512; k += 256) {
        int r  = k >> 7;             // 0..3
        int f4 = k & 127;            // float4 within row
        int y  = 2 * py - 1 + r;
        float4 v = make_float4(0.f, 0.f, 0.f, 0.f);
        if (y >= 0 && y < 512)
            v = __ldg((const float4*)(s + y * 512) + f4);
        float* dst = &srow[r][1 + 4 * f4];
        dst[0] = v.x; dst[1] = v.y; dst[2] = v.z; dst[3] = v.w;
    }
    if (tid < 8) {                   // halo columns x=-1, x=512 are always zero
        int r = tid >> 1;
        srow[r][(tid & 1) ? 513 : 0] = 0.f;
    }
    __syncthreads();

    // Each thread: one pooled pixel. patch x base = 2*px-1 -> smem idx 2*px
    {
        int xb = 2 * tid;
        const float* r0 = srow[0], *r1 = srow[1], *r2 = srow[2], *r3 = srow[3];
        float m = fmaxf(
            fmaxf(edge_at(r0, r1, r2, xb),     edge_at(r0, r1, r2, xb + 1)),
            fmaxf(edge_at(r1, r2, r3, xb),     edge_at(r1, r2, r3, xb + 1)));
        row[tid] = m;
    }
    __syncthreads();

    // Broadcast write: 128 channels x 64 float4 = 8192 float4 / block.
    int px4  = tid & 63;
    int csub = tid >> 6;             // 0..3
    float4 v = ((const float4*)row)[px4];
    // out index for (b, c, py, px4): ((b*128 + c)*256 + py)*64 + px4
    float4* o = out + ((size_t)(b * NCH + csub) * 256 + py) * 64 + px4;
#pragma unroll
    for (int i = 0; i < 32; i++) {
        __stcs(o, v);                // evict-first: start writeback now
        o += (size_t)4 * 256 * 64;   // advance 4 channels
    }
}

extern "C" void kernel_launch(void* const* d_in, const int* in_sizes, int n_in,
                              void* d_out, int out_size) {
    const float4* x = (const float4*)d_in[0];
    float4* out = (float4*)d_out;

    k_chansum<<<(NB * S_SPATIAL4 + 255) / 256, 256>>>(x);
    k_edgecast<<<NB * 256, 256>>>(out);
}